// round 1
// baseline (speedup 1.0000x reference)
#include <cuda_runtime.h>
#include <math.h>

// Problem constants
#define B_    4
#define H_    128
#define W_    128
#define C_    256
#define NH_   8
#define HD_   32
#define HW_   (H_ * W_)                 // 16384
#define NWIN  (B_ * H_)                 // 512
#define NCTA  (NWIN * NH_)              // 4096
#define QKV_STRIDE ((size_t)B_ * HW_ * C_)   // 16,777,216 floats between q/k/v

// Scratch: attn logits (512 win * 8 heads * 128 * 128 floats = 268 MB)
__device__ float g_attn[(size_t)NCTA * W_ * W_];
__device__ float g_wsum[NWIN];
__device__ float g_M[NWIN];

// ---------------------------------------------------------------------------
// Kernel 0: zero the per-window |attn| accumulators (graph replays need reset)
// ---------------------------------------------------------------------------
__global__ void zero_kernel() {
    g_wsum[threadIdx.x] = 0.0f;
}

// ---------------------------------------------------------------------------
// Kernel 1: per (window, head) QK^T + RPE bias -> g_attn, plus per-window
// sum of |attn| via block reduce + atomicAdd.
// One CTA = one (window, head). 256 threads, each computes an 8x8 tile of the
// 128x128 logits. Q/K staged in smem transposed ([d][w]) for vectorized frags.
// ---------------------------------------------------------------------------
__global__ __launch_bounds__(256) void attn_kernel(const float* __restrict__ qkv) {
    __shared__ float Qs[32][132];
    __shared__ float Ks[32][132];
    __shared__ float magt[256];
    __shared__ float wsum[8];

    const int bx  = blockIdx.x;        // 0..4095
    const int wi  = bx >> 3;           // window
    const int n   = bx & 7;            // head
    const int b   = wi >> 7;
    const int h   = wi & 127;
    const int tid = threadIdx.x;

    // RPE magnitude table: delta(q,k) = (k - q) * 2*pi/127
    if (tid < 255) {
        float delta = (float)(tid - 127) * (6.283185307179586477f / 127.0f);
        magt[tid] = sqrtf(fmaxf(2.0f - 2.0f * cosf(delta), 0.0f));
    }

    // Stage Q and K (each 128 rows x 32 floats) transposed into smem.
    const float* qb = qkv + ((size_t)(b * HW_) + (size_t)h * W_) * C_ + n * HD_;
    const float* kb = qb + QKV_STRIDE;
    #pragma unroll
    for (int t = 0; t < 4; ++t) {
        int idx = tid + t * 256;       // 0..1023 float4 chunks
        int w   = idx >> 3;            // row 0..127
        int d4  = (idx & 7) << 2;      // 0,4,...,28
        float4 qv = *(const float4*)(qb + (size_t)w * C_ + d4);
        float4 kv = *(const float4*)(kb + (size_t)w * C_ + d4);
        Qs[d4 + 0][w] = qv.x; Qs[d4 + 1][w] = qv.y;
        Qs[d4 + 2][w] = qv.z; Qs[d4 + 3][w] = qv.w;
        Ks[d4 + 0][w] = kv.x; Ks[d4 + 1][w] = kv.y;
        Ks[d4 + 2][w] = kv.z; Ks[d4 + 3][w] = kv.w;
    }
    __syncthreads();

    const int kx = tid & 15;
    const int qy = tid >> 4;
    const int q0 = qy << 3;
    const int k0 = kx << 3;

    float acc[8][8];
    #pragma unroll
    for (int i = 0; i < 8; ++i)
        #pragma unroll
        for (int j = 0; j < 8; ++j) acc[i][j] = 0.0f;

    #pragma unroll 4
    for (int kk = 0; kk < 32; ++kk) {
        __align__(16) float af[8], bf[8];
        *(float4*)(af)     = *(const float4*)(&Qs[kk][q0]);
        *(float4*)(af + 4) = *(const float4*)(&Qs[kk][q0 + 4]);
        *(float4*)(bf)     = *(const float4*)(&Ks[kk][k0]);
        *(float4*)(bf + 4) = *(const float4*)(&Ks[kk][k0 + 4]);
        #pragma unroll
        for (int i = 0; i < 8; ++i)
            #pragma unroll
            for (int j = 0; j < 8; ++j)
                acc[i][j] = fmaf(af[i], bf[j], acc[i][j]);
    }

    // Bias + |.| accumulation + store
    const float bscale = 0.1f * sinf((float)h * (3.14159265358979323846f / 128.0f));
    float* ao = g_attn + (size_t)bx * (W_ * W_);
    float s_abs = 0.0f;
    #pragma unroll
    for (int i = 0; i < 8; ++i) {
        const int q = q0 + i;
        __align__(16) float row[8];
        #pragma unroll
        for (int j = 0; j < 8; ++j) {
            const int k = k0 + j;
            float bias = ((k > q) ? bscale : -bscale) * magt[k - q + 127];
            float v = acc[i][j] + bias;
            row[j] = v;
            s_abs += fabsf(v);
        }
        *(float4*)(ao + (size_t)q * W_ + k0)     = *(float4*)(row);
        *(float4*)(ao + (size_t)q * W_ + k0 + 4) = *(float4*)(row + 4);
    }

    #pragma unroll
    for (int m = 16; m; m >>= 1)
        s_abs += __shfl_xor_sync(0xffffffffu, s_abs, m);
    if ((tid & 31) == 0) wsum[tid >> 5] = s_abs;
    __syncthreads();
    if (tid == 0) {
        float s = 0.0f;
        #pragma unroll
        for (int i = 0; i < 8; ++i) s += wsum[i];
        atomicAdd(&g_wsum[wi], s);
    }
}

// ---------------------------------------------------------------------------
// Kernel 2: gate computation. 512 windows -> mean, global max, M = max(m/mx, .5)
// ---------------------------------------------------------------------------
__global__ void gate_kernel() {
    __shared__ float red[512];
    const int t = threadIdx.x;
    float mean = g_wsum[t] * (1.0f / 131072.0f);  // / (NH*W*W)
    red[t] = mean;
    __syncthreads();
    for (int s = 256; s > 0; s >>= 1) {
        if (t < s) red[t] = fmaxf(red[t], red[t + s]);
        __syncthreads();
    }
    float mx = red[0];
    g_M[t] = fmaxf(mean / mx, 0.5f);
}

// ---------------------------------------------------------------------------
// Kernel 3: read attn, per-row L2 normalize, (1 - cos(a/||a|| * pi/2)) * M,
// multiply by V (128x128 @ 128x32), add gated residual, write output.
// One CTA = one (window, head). Transform phase writes the transformed attn
// to smem, then a register-tiled GEMM against V.
// ---------------------------------------------------------------------------
#define AV_SMEM ((128 * 132 + 128 * 32) * 4)   // 83,968 bytes

__global__ __launch_bounds__(256) void av_kernel(const float* __restrict__ qkv,
                                                 const float* __restrict__ resx,
                                                 float* __restrict__ out) {
    extern __shared__ float sm[];
    float* As = sm;                 // [128][132] transformed attn
    float* Vs = sm + 128 * 132;     // [128][32]

    const int bx  = blockIdx.x;
    const int wi  = bx >> 3;
    const int n   = bx & 7;
    const int b   = wi >> 7;
    const int h   = wi & 127;
    const int tid = threadIdx.x;

    // Load V tile
    const float* vb = qkv + 2 * QKV_STRIDE +
                      ((size_t)(b * HW_) + (size_t)h * W_) * C_ + n * HD_;
    #pragma unroll
    for (int t = 0; t < 4; ++t) {
        int idx = tid + t * 256;
        int k   = idx >> 3;
        int d4  = (idx & 7) << 2;
        *(float4*)(Vs + k * 32 + d4) = *(const float4*)(vb + (size_t)k * C_ + d4);
    }

    const float Mw   = g_M[wi];
    const float oneM = 1.0f - Mw;

    // Transform phase: 8x8 tile per thread
    const int kx = tid & 15;
    const int qy = tid >> 4;
    const int q0 = qy << 3;
    const int k0 = kx << 3;
    const float* ai = g_attn + (size_t)bx * (W_ * W_);

    __align__(16) float vals[8][8];
    float ss[8];
    #pragma unroll
    for (int i = 0; i < 8; ++i) {
        float4 v0 = *(const float4*)(ai + (size_t)(q0 + i) * W_ + k0);
        float4 v1 = *(const float4*)(ai + (size_t)(q0 + i) * W_ + k0 + 4);
        vals[i][0] = v0.x; vals[i][1] = v0.y; vals[i][2] = v0.z; vals[i][3] = v0.w;
        vals[i][4] = v1.x; vals[i][5] = v1.y; vals[i][6] = v1.z; vals[i][7] = v1.w;
        ss[i] = v0.x * v0.x + v0.y * v0.y + v0.z * v0.z + v0.w * v0.w
              + v1.x * v1.x + v1.y * v1.y + v1.z * v1.z + v1.w * v1.w;
    }
    // Row sum-of-squares across the 16 kx lanes (xor <= 8 stays in 16-lane group)
    #pragma unroll
    for (int m = 1; m < 16; m <<= 1)
        #pragma unroll
        for (int i = 0; i < 8; ++i)
            ss[i] += __shfl_xor_sync(0xffffffffu, ss[i], m);

    #pragma unroll
    for (int i = 0; i < 8; ++i) {
        float inv = 1.57079632679489662f / fmaxf(sqrtf(ss[i]), 1e-12f);
        __align__(16) float row[8];
        #pragma unroll
        for (int j = 0; j < 8; ++j)
            row[j] = (1.0f - __cosf(vals[i][j] * inv)) * Mw;
        *(float4*)(As + (q0 + i) * 132 + k0)     = *(float4*)(row);
        *(float4*)(As + (q0 + i) * 132 + k0 + 4) = *(float4*)(row + 4);
    }
    __syncthreads();

    // GEMM phase: out[128 q][32 d], thread tile 4x4
    const int qg = (tid >> 3) << 2;   // 0..124
    const int dg = (tid & 7) << 2;    // 0..28
    float acc[4][4];
    #pragma unroll
    for (int i = 0; i < 4; ++i)
        #pragma unroll
        for (int j = 0; j < 4; ++j) acc[i][j] = 0.0f;

    #pragma unroll 4
    for (int kk = 0; kk < 128; kk += 4) {
        __align__(16) float aa[4][4];
        #pragma unroll
        for (int i = 0; i < 4; ++i)
            *(float4*)(aa[i]) = *(const float4*)(As + (qg + i) * 132 + kk);
        #pragma unroll
        for (int t = 0; t < 4; ++t) {
            float4 bv = *(const float4*)(Vs + (kk + t) * 32 + dg);
            #pragma unroll
            for (int i = 0; i < 4; ++i) {
                acc[i][0] = fmaf(aa[i][t], bv.x, acc[i][0]);
                acc[i][1] = fmaf(aa[i][t], bv.y, acc[i][1]);
                acc[i][2] = fmaf(aa[i][t], bv.z, acc[i][2]);
                acc[i][3] = fmaf(aa[i][t], bv.w, acc[i][3]);
            }
        }
    }

    // Output + gated residual
    const size_t obase = ((size_t)(b * HW_) + (size_t)h * W_) * C_ + n * HD_;
    #pragma unroll
    for (int i = 0; i < 4; ++i) {
        const int q = qg + i;
        const float* rp = resx + obase + (size_t)q * C_ + dg;
        __align__(16) float o[4];
        o[0] = acc[i][0] + rp[0] * oneM;
        o[1] = acc[i][1] + rp[1] * oneM;
        o[2] = acc[i][2] + rp[2] * oneM;
        o[3] = acc[i][3] + rp[3] * oneM;
        *(float4*)(out + obase + (size_t)q * C_ + dg) = *(float4*)o;
    }
}

// ---------------------------------------------------------------------------
extern "C" void kernel_launch(void* const* d_in, const int* in_sizes, int n_in,
                              void* d_out, int out_size) {
    (void)in_sizes; (void)n_in; (void)out_size;
    const float* qkv  = (const float*)d_in[0];
    const float* resx = (const float*)d_in[1];
    float* out = (float*)d_out;

    cudaFuncSetAttribute(av_kernel, cudaFuncAttributeMaxDynamicSharedMemorySize, AV_SMEM);

    zero_kernel<<<1, NWIN>>>();
    attn_kernel<<<NCTA, 256>>>(qkv);
    gate_kernel<<<1, NWIN>>>();
    av_kernel<<<NCTA, 256, AV_SMEM>>>(qkv, resx, out);
}

// round 2
// speedup vs baseline: 1.2427x; 1.2427x over previous
#include <cuda_runtime.h>
#include <cuda_fp16.h>
#include <math.h>

// Problem constants
#define B_    4
#define H_    128
#define W_    128
#define C_    256
#define NH_   8
#define HD_   32
#define HW_   (H_ * W_)                 // 16384
#define NWIN  (B_ * H_)                 // 512
#define NCTA  (NWIN * NH_)              // 4096
#define QKV_STRIDE ((size_t)B_ * HW_ * C_)   // 16,777,216 floats between q/k/v

// Scratch: attn logits in fp16 (512 win * 8 heads * 128 * 128 = 134 MB)
__device__ __align__(16) __half g_attnh[(size_t)NCTA * W_ * W_];
__device__ float g_wsum[NWIN];
__device__ float g_M[NWIN];

// Packed f32x2 FMA helpers (sm_103a; ptxas never emits FFMA2 from C++)
#define FFMA2(d, a, b) \
    asm volatile("fma.rn.f32x2 %0, %1, %2, %0;" : "+l"(d) : "l"(a), "l"(b))
#define BCAST2(d, x) \
    asm volatile("mov.b64 %0, {%1, %1};" : "=l"(d) : "r"(__float_as_uint(x)))
#define UNPK2(lo, hi, v) \
    asm volatile("mov.b64 {%0, %1}, %2;" : "=r"(lo), "=r"(hi) : "l"(v))

// ---------------------------------------------------------------------------
// Kernel 1: per (window, head) QK^T + RPE bias -> g_attnh (fp16), plus
// per-window sum of |attn| via block reduce + atomicAdd.
// One CTA = one (window, head); 256 threads, 8x8 tile each, FFMA2 inner loop.
// ---------------------------------------------------------------------------
__global__ __launch_bounds__(256) void attn_kernel(const float* __restrict__ qkv) {
    __shared__ float Qs[32][132];
    __shared__ float Ks[32][132];
    __shared__ float magt[256];
    __shared__ float wsum[8];

    const int bx  = blockIdx.x;        // 0..4095
    const int wi  = bx >> 3;           // window
    const int n   = bx & 7;            // head
    const int b   = wi >> 7;
    const int h   = wi & 127;
    const int tid = threadIdx.x;

    // RPE magnitude table: delta(q,k) = (k - q) * 2*pi/127
    if (tid < 255) {
        float delta = (float)(tid - 127) * (6.283185307179586477f / 127.0f);
        magt[tid] = sqrtf(fmaxf(2.0f - 2.0f * cosf(delta), 0.0f));
    }

    // Stage Q and K (each 128 rows x 32 floats) transposed into smem.
    const float* qb = qkv + ((size_t)(b * HW_) + (size_t)h * W_) * C_ + n * HD_;
    const float* kb = qb + QKV_STRIDE;
    #pragma unroll
    for (int t = 0; t < 4; ++t) {
        int idx = tid + t * 256;       // 0..1023 float4 chunks
        int w   = idx >> 3;            // row 0..127
        int d4  = (idx & 7) << 2;      // 0,4,...,28
        float4 qv = *(const float4*)(qb + (size_t)w * C_ + d4);
        float4 kv = *(const float4*)(kb + (size_t)w * C_ + d4);
        Qs[d4 + 0][w] = qv.x; Qs[d4 + 1][w] = qv.y;
        Qs[d4 + 2][w] = qv.z; Qs[d4 + 3][w] = qv.w;
        Ks[d4 + 0][w] = kv.x; Ks[d4 + 1][w] = kv.y;
        Ks[d4 + 2][w] = kv.z; Ks[d4 + 3][w] = kv.w;
    }
    __syncthreads();

    const int kx = tid & 15;
    const int qy = tid >> 4;
    const int q0 = qy << 3;
    const int k0 = kx << 3;

    unsigned long long acc2[8][4];
    #pragma unroll
    for (int i = 0; i < 8; ++i)
        #pragma unroll
        for (int j = 0; j < 4; ++j) acc2[i][j] = 0ULL;

    #pragma unroll 4
    for (int kk = 0; kk < 32; ++kk) {
        float4 a0 = *(const float4*)(&Qs[kk][q0]);
        float4 a1 = *(const float4*)(&Qs[kk][q0 + 4]);
        ulonglong2 bA = *(const ulonglong2*)(&Ks[kk][k0]);
        ulonglong2 bB = *(const ulonglong2*)(&Ks[kk][k0 + 4]);
        const unsigned long long bb0 = bA.x, bb1 = bA.y, bb2 = bB.x, bb3 = bB.y;
        float af[8] = {a0.x, a0.y, a0.z, a0.w, a1.x, a1.y, a1.z, a1.w};
        #pragma unroll
        for (int i = 0; i < 8; ++i) {
            unsigned long long ad;
            BCAST2(ad, af[i]);
            FFMA2(acc2[i][0], ad, bb0);
            FFMA2(acc2[i][1], ad, bb1);
            FFMA2(acc2[i][2], ad, bb2);
            FFMA2(acc2[i][3], ad, bb3);
        }
    }

    // Bias + |.| accumulation + fp16 store
    const float bscale = 0.1f * sinf((float)h * (3.14159265358979323846f / 128.0f));
    __half* ao = g_attnh + (size_t)bx * (W_ * W_);
    float s_abs = 0.0f;
    #pragma unroll
    for (int i = 0; i < 8; ++i) {
        const int q = q0 + i;
        float row[8];
        #pragma unroll
        for (int j2 = 0; j2 < 4; ++j2) {
            unsigned int lo, hi;
            UNPK2(lo, hi, acc2[i][j2]);
            row[2 * j2]     = __uint_as_float(lo);
            row[2 * j2 + 1] = __uint_as_float(hi);
        }
        union { half2 h[4]; uint4 u; } cvt;
        #pragma unroll
        for (int j2 = 0; j2 < 4; ++j2) {
            float v0, v1;
            {
                const int k = k0 + 2 * j2;
                float bias = ((k > q) ? bscale : -bscale) * magt[k - q + 127];
                v0 = row[2 * j2] + bias;
            }
            {
                const int k = k0 + 2 * j2 + 1;
                float bias = ((k > q) ? bscale : -bscale) * magt[k - q + 127];
                v1 = row[2 * j2 + 1] + bias;
            }
            s_abs += fabsf(v0) + fabsf(v1);
            cvt.h[j2] = __floats2half2_rn(v0, v1);
        }
        *(uint4*)(ao + (size_t)q * W_ + k0) = cvt.u;
    }

    #pragma unroll
    for (int m = 16; m; m >>= 1)
        s_abs += __shfl_xor_sync(0xffffffffu, s_abs, m);
    if ((tid & 31) == 0) wsum[tid >> 5] = s_abs;
    __syncthreads();
    if (tid == 0) {
        float s = 0.0f;
        #pragma unroll
        for (int i = 0; i < 8; ++i) s += wsum[i];
        atomicAdd(&g_wsum[wi], s);
    }
}

// ---------------------------------------------------------------------------
// Kernel 2: gate. 512 windows -> mean, global max, M = max(m/mx, .5).
// Also resets g_wsum for the next graph replay (keeps launch count at 3).
// ---------------------------------------------------------------------------
__global__ void gate_kernel() {
    __shared__ float red[512];
    const int t = threadIdx.x;
    float mean = g_wsum[t] * (1.0f / 131072.0f);  // / (NH*W*W)
    g_wsum[t] = 0.0f;                             // reset for next replay
    red[t] = mean;
    __syncthreads();
    for (int s = 256; s > 0; s >>= 1) {
        if (t < s) red[t] = fmaxf(red[t], red[t + s]);
        __syncthreads();
    }
    float mx = red[0];
    g_M[t] = fmaxf(mean / mx, 0.5f);
}

// ---------------------------------------------------------------------------
// Kernel 3: read fp16 attn, per-row L2 normalize, (1-cos(a/||a||*pi/2))*M,
// multiply by V (128x128 @ 128x32) with FFMA2, add gated residual.
// ---------------------------------------------------------------------------
#define AV_SMEM ((128 * 132 + 128 * 32) * 4)   // 83,968 bytes

__global__ __launch_bounds__(256) void av_kernel(const float* __restrict__ qkv,
                                                 const float* __restrict__ resx,
                                                 float* __restrict__ out) {
    extern __shared__ float sm[];
    float* As = sm;                 // [128][132] transformed attn
    float* Vs = sm + 128 * 132;     // [128][32]

    const int bx  = blockIdx.x;
    const int wi  = bx >> 3;
    const int n   = bx & 7;
    const int b   = wi >> 7;
    const int h   = wi & 127;
    const int tid = threadIdx.x;

    // Load V tile
    const float* vb = qkv + 2 * QKV_STRIDE +
                      ((size_t)(b * HW_) + (size_t)h * W_) * C_ + n * HD_;
    #pragma unroll
    for (int t = 0; t < 4; ++t) {
        int idx = tid + t * 256;
        int k   = idx >> 3;
        int d4  = (idx & 7) << 2;
        *(float4*)(Vs + k * 32 + d4) = *(const float4*)(vb + (size_t)k * C_ + d4);
    }

    const float Mw   = g_M[wi];
    const float oneM = 1.0f - Mw;

    // Transform phase: 8x8 tile per thread
    const int kx = tid & 15;
    const int qy = tid >> 4;
    const int q0 = qy << 3;
    const int k0 = kx << 3;
    const __half* ai = g_attnh + (size_t)bx * (W_ * W_);

    float vals[8][8];
    float ss[8];
    #pragma unroll
    for (int i = 0; i < 8; ++i) {
        uint4 hv = *(const uint4*)(ai + (size_t)(q0 + i) * W_ + k0);
        const half2* hp = reinterpret_cast<const half2*>(&hv);
        float s = 0.0f;
        #pragma unroll
        for (int j2 = 0; j2 < 4; ++j2) {
            float2 f = __half22float2(hp[j2]);
            vals[i][2 * j2]     = f.x;
            vals[i][2 * j2 + 1] = f.y;
            s += f.x * f.x + f.y * f.y;
        }
        ss[i] = s;
    }
    // Row sum-of-squares across the 16 kx lanes
    #pragma unroll
    for (int m = 1; m < 16; m <<= 1)
        #pragma unroll
        for (int i = 0; i < 8; ++i)
            ss[i] += __shfl_xor_sync(0xffffffffu, ss[i], m);

    #pragma unroll
    for (int i = 0; i < 8; ++i) {
        float inv = 1.57079632679489662f / fmaxf(sqrtf(ss[i]), 1e-12f);
        __align__(16) float row[8];
        #pragma unroll
        for (int j = 0; j < 8; ++j)
            row[j] = (1.0f - __cosf(vals[i][j] * inv)) * Mw;
        *(float4*)(As + (q0 + i) * 132 + k0)     = *(float4*)(row);
        *(float4*)(As + (q0 + i) * 132 + k0 + 4) = *(float4*)(row + 4);
    }
    __syncthreads();

    // GEMM phase: out[128 q][32 d], thread tile 4x4, FFMA2 along d
    const int qg = (tid >> 3) << 2;   // 0..124
    const int dg = (tid & 7) << 2;    // 0..28
    unsigned long long acc2[4][2];
    #pragma unroll
    for (int i = 0; i < 4; ++i) { acc2[i][0] = 0ULL; acc2[i][1] = 0ULL; }

    #pragma unroll 4
    for (int kkb = 0; kkb < 128; kkb += 4) {
        __align__(16) float aa[4][4];
        #pragma unroll
        for (int i = 0; i < 4; ++i)
            *(float4*)(aa[i]) = *(const float4*)(As + (qg + i) * 132 + kkb);
        #pragma unroll
        for (int t = 0; t < 4; ++t) {
            ulonglong2 bv = *(const ulonglong2*)(Vs + (kkb + t) * 32 + dg);
            #pragma unroll
            for (int i = 0; i < 4; ++i) {
                unsigned long long ad;
                BCAST2(ad, aa[i][t]);
                FFMA2(acc2[i][0], ad, bv.x);
                FFMA2(acc2[i][1], ad, bv.y);
            }
        }
    }

    // Output + gated residual
    const size_t obase = ((size_t)(b * HW_) + (size_t)h * W_) * C_ + n * HD_;
    #pragma unroll
    for (int i = 0; i < 4; ++i) {
        const int q = qg + i;
        float acc[4];
        unsigned int lo, hi;
        UNPK2(lo, hi, acc2[i][0]);
        acc[0] = __uint_as_float(lo); acc[1] = __uint_as_float(hi);
        UNPK2(lo, hi, acc2[i][1]);
        acc[2] = __uint_as_float(lo); acc[3] = __uint_as_float(hi);

        const float* rp = resx + obase + (size_t)q * C_ + dg;
        __align__(16) float o[4];
        o[0] = acc[0] + rp[0] * oneM;
        o[1] = acc[1] + rp[1] * oneM;
        o[2] = acc[2] + rp[2] * oneM;
        o[3] = acc[3] + rp[3] * oneM;
        *(float4*)(out + obase + (size_t)q * C_ + dg) = *(float4*)o;
    }
}

// ---------------------------------------------------------------------------
extern "C" void kernel_launch(void* const* d_in, const int* in_sizes, int n_in,
                              void* d_out, int out_size) {
    (void)in_sizes; (void)n_in; (void)out_size;
    const float* qkv  = (const float*)d_in[0];
    const float* resx = (const float*)d_in[1];
    float* out = (float*)d_out;

    cudaFuncSetAttribute(av_kernel, cudaFuncAttributeMaxDynamicSharedMemorySize, AV_SMEM);

    attn_kernel<<<NCTA, 256>>>(qkv);
    gate_kernel<<<1, NWIN>>>();
    av_kernel<<<NCTA, 256, AV_SMEM>>>(qkv, resx, out);
}